// round 1
// baseline (speedup 1.0000x reference)
#include <cuda_runtime.h>
#include <math.h>

// ---------------- problem constants ----------------
#define KSEQ 1024
#define KBATCH 4
#define KHID 2048
#define KNH 16
#define KKVH 4
#define KHD 128
#define KINT 8192
#define KM (KBATCH*KSEQ)   // 4096 rows

// ---------------- scratch (device globals; no cudaMalloc allowed) ----------
__device__ float g_attn_in[(size_t)KM * KHID];
__device__ float g_q[(size_t)KM * KNH * KHD];
__device__ float g_k[(size_t)KM * KKVH * KHD];
__device__ float g_v[(size_t)KM * KKVH * KHD];
__device__ float g_ctx[(size_t)KM * KNH * KHD];
__device__ float g_mlp_in[(size_t)KM * KHID];
__device__ float g_gu[(size_t)KM * 2 * KINT];

// ---------------- f32x2 packed-FMA helpers (Blackwell 2x fp32 path) --------
__device__ __forceinline__ unsigned long long pk2(float x, float y) {
    unsigned long long r;
    asm("mov.b64 %0, {%1, %2};" : "=l"(r) : "f"(x), "f"(y));
    return r;
}
__device__ __forceinline__ void unpk2(unsigned long long p, float& x, float& y) {
    asm("mov.b64 {%0, %1}, %2;" : "=f"(x), "=f"(y) : "l"(p));
}
__device__ __forceinline__ void ffma2(unsigned long long& d, unsigned long long a,
                                      unsigned long long b) {
    asm("fma.rn.f32x2 %0, %1, %2, %3;" : "=l"(d) : "l"(a), "l"(b), "l"(d));
}

// ---------------- RMSNorm: one block per row ----------------
__global__ __launch_bounds__(256) void rmsnorm_kernel(const float* __restrict__ x,
                                                      const float* __restrict__ w,
                                                      float* __restrict__ y) {
    int row = blockIdx.x;
    const float4* xr = (const float4*)(x + (size_t)row * KHID);
    const float4* w4 = (const float4*)w;
    float4* yr = (float4*)(y + (size_t)row * KHID);
    int t = threadIdx.x;

    float4 a = xr[t];
    float4 b = xr[t + 256];
    float ss = a.x * a.x + a.y * a.y + a.z * a.z + a.w * a.w +
               b.x * b.x + b.y * b.y + b.z * b.z + b.w * b.w;
#pragma unroll
    for (int off = 16; off; off >>= 1) ss += __shfl_xor_sync(0xffffffffu, ss, off);
    __shared__ float wsum[8];
    if ((t & 31) == 0) wsum[t >> 5] = ss;
    __syncthreads();
    float tot = wsum[0] + wsum[1] + wsum[2] + wsum[3] +
                wsum[4] + wsum[5] + wsum[6] + wsum[7];
    float inv = rsqrtf(tot * (1.0f / KHID) + 1e-6f);

    float4 wa = w4[t], wb = w4[t + 256];
    yr[t] = make_float4(a.x * inv * wa.x, a.y * inv * wa.y, a.z * inv * wa.z, a.w * inv * wa.w);
    yr[t + 256] = make_float4(b.x * inv * wb.x, b.y * inv * wb.y, b.z * inv * wb.z, b.w * inv * wb.w);
}

// ---------------- RoPE (in place) ----------------
__global__ void rope_kernel(float* __restrict__ x, const float* __restrict__ sin_t,
                            const float* __restrict__ cos_t, int nheads, int total) {
    int idx = blockIdx.x * blockDim.x + threadIdx.x;
    if (idx >= total) return;
    int half = idx & 63;
    int t2 = idx >> 6;
    int hh = t2 % nheads;
    int row = t2 / nheads;          // b*KSEQ + s
    int s = row & (KSEQ - 1);
    float* p = x + (size_t)row * nheads * KHD + hh * KHD;
    float c = cos_t[s * 64 + half];
    float si = sin_t[s * 64 + half];
    float x1 = p[half], x2 = p[half + 64];
    p[half] = x1 * c - x2 * si;
    p[half + 64] = x2 * c + x1 * si;
}

// ---------------- GEMM: C[M,N] = A[M,K] * B[N,K]^T (+R), fp32 via f32x2 ----
// FUSE==1: A element = silu(gu[m,k]) * gu[m,k+KINT]   (down-proj)
#define BM 128
#define BN 128
#define BK 16

template <int FUSE>
__global__ __launch_bounds__(256, 2) void gemm_nt(const float* __restrict__ A, int lda,
                                                  const float* __restrict__ B, int ldb,
                                                  const float* __restrict__ R,
                                                  float* __restrict__ C, int ldc, int K) {
    __shared__ float As[BK][BM + 4];
    __shared__ float Bs[BK][BN + 4];

    int bm = blockIdx.x * BM;   // M fastest -> B panel reused across x-sweep
    int bn = blockIdx.y * BN;
    int tid = threadIdx.x;
    int row0 = (tid >> 4) * 8;
    int col0 = (tid & 15) * 8;

    unsigned long long acc[8][4];
#pragma unroll
    for (int i = 0; i < 8; i++)
#pragma unroll
        for (int j = 0; j < 4; j++) acc[i][j] = 0ull;

    int lrow = tid >> 2;          // 0..63
    int lk4 = (tid & 3) * 4;      // 0,4,8,12

    for (int k0 = 0; k0 < K; k0 += BK) {
#pragma unroll
        for (int h = 0; h < 2; h++) {
            int r = lrow + h * 64;
            float4 va;
            if (FUSE == 0) {
                va = *(const float4*)&A[(size_t)(bm + r) * lda + k0 + lk4];
            } else {
                float4 g = *(const float4*)&A[(size_t)(bm + r) * lda + k0 + lk4];
                float4 u = *(const float4*)&A[(size_t)(bm + r) * lda + k0 + lk4 + KINT];
                va.x = (g.x / (1.0f + __expf(-g.x))) * u.x;
                va.y = (g.y / (1.0f + __expf(-g.y))) * u.y;
                va.z = (g.z / (1.0f + __expf(-g.z))) * u.z;
                va.w = (g.w / (1.0f + __expf(-g.w))) * u.w;
            }
            As[lk4 + 0][r] = va.x;
            As[lk4 + 1][r] = va.y;
            As[lk4 + 2][r] = va.z;
            As[lk4 + 3][r] = va.w;
            float4 vb = *(const float4*)&B[(size_t)(bn + r) * ldb + k0 + lk4];
            Bs[lk4 + 0][r] = vb.x;
            Bs[lk4 + 1][r] = vb.y;
            Bs[lk4 + 2][r] = vb.z;
            Bs[lk4 + 3][r] = vb.w;
        }
        __syncthreads();
#pragma unroll
        for (int kk = 0; kk < BK; kk++) {
            float4 a0 = *(const float4*)&As[kk][row0];
            float4 a1 = *(const float4*)&As[kk][row0 + 4];
            float4 b0 = *(const float4*)&Bs[kk][col0];
            float4 b1 = *(const float4*)&Bs[kk][col0 + 4];
            unsigned long long bb0 = pk2(b0.x, b0.y);
            unsigned long long bb1 = pk2(b0.z, b0.w);
            unsigned long long bb2 = pk2(b1.x, b1.y);
            unsigned long long bb3 = pk2(b1.z, b1.w);
            float av[8] = {a0.x, a0.y, a0.z, a0.w, a1.x, a1.y, a1.z, a1.w};
#pragma unroll
            for (int i = 0; i < 8; i++) {
                unsigned long long aa = pk2(av[i], av[i]);
                ffma2(acc[i][0], aa, bb0);
                ffma2(acc[i][1], aa, bb1);
                ffma2(acc[i][2], aa, bb2);
                ffma2(acc[i][3], aa, bb3);
            }
        }
        __syncthreads();
    }

#pragma unroll
    for (int i = 0; i < 8; i++) {
        float cv[8];
#pragma unroll
        for (int j = 0; j < 4; j++) unpk2(acc[i][j], cv[2 * j], cv[2 * j + 1]);
        size_t off = (size_t)(bm + row0 + i) * ldc + bn + col0;
        if (R != nullptr) {
#pragma unroll
            for (int j = 0; j < 8; j++) cv[j] += R[off + j];
        }
        *(float4*)&C[off] = make_float4(cv[0], cv[1], cv[2], cv[3]);
        *(float4*)&C[off + 4] = make_float4(cv[4], cv[5], cv[6], cv[7]);
    }
}

// ---------------- causal GQA flash attention, fp32 ----------------
// grid (KSEQ/64, KNH, KBATCH), 256 threads.
#define ATTN_SMEM_FLOATS (2 * 64 * 132 + 64 * 68)

__global__ __launch_bounds__(256) void attn_kernel(const float* __restrict__ q,
                                                   const float* __restrict__ kmat,
                                                   const float* __restrict__ vmat,
                                                   float* __restrict__ ctx) {
    extern __shared__ float sm[];
    float(*Qs)[132] = (float(*)[132])sm;
    float(*KVs)[132] = (float(*)[132])(sm + 64 * 132);
    float(*Ps)[68] = (float(*)[68])(sm + 2 * 64 * 132);

    int m0 = blockIdx.x * 64;
    int head = blockIdx.y;
    int b = blockIdx.z;
    int kvh = head >> 2;    // NH/KVH = 4
    const float* qb = q + (size_t)(b * KSEQ + m0) * (KNH * KHD) + head * KHD;
    const float* kb = kmat + (size_t)(b * KSEQ) * (KKVH * KHD) + kvh * KHD;
    const float* vb = vmat + (size_t)(b * KSEQ) * (KKVH * KHD) + kvh * KHD;

    int tid = threadIdx.x;
    int ty = tid >> 4, tx = tid & 15;
    int r0 = ty * 4;
    int d0 = tx * 8;
    const float scale = 0.08838834764831845f;  // 1/sqrt(128)

    // load Q tile (pre-scaled)
    for (int idx = tid; idx < 64 * 32; idx += 256) {
        int r = idx >> 5, c4 = (idx & 31) * 4;
        float4 v = *(const float4*)&qb[(size_t)r * (KNH * KHD) + c4];
        v.x *= scale; v.y *= scale; v.z *= scale; v.w *= scale;
        *(float4*)&Qs[r][c4] = v;
    }

    float acc_o[4][8];
#pragma unroll
    for (int i = 0; i < 4; i++)
#pragma unroll
        for (int j = 0; j < 8; j++) acc_o[i][j] = 0.0f;
    float mrow[4], lrow[4];
#pragma unroll
    for (int i = 0; i < 4; i++) { mrow[i] = -1e30f; lrow[i] = 0.0f; }

    int ntiles = blockIdx.x + 1;
    for (int nt = 0; nt < ntiles; nt++) {
        int n0 = nt * 64;
        __syncthreads();   // prior PV done with KVs
        for (int idx = tid; idx < 64 * 32; idx += 256) {
            int r = idx >> 5, c4 = (idx & 31) * 4;
            *(float4*)&KVs[r][c4] = *(const float4*)&kb[(size_t)(n0 + r) * (KKVH * KHD) + c4];
        }
        __syncthreads();   // Qs (iter 0) + K tile ready

        float accs[4][4];
#pragma unroll
        for (int i = 0; i < 4; i++)
#pragma unroll
            for (int j = 0; j < 4; j++) accs[i][j] = 0.0f;

        for (int kk = 0; kk < 128; kk += 4) {
            float4 qv[4], kv[4];
#pragma unroll
            for (int i = 0; i < 4; i++) qv[i] = *(const float4*)&Qs[r0 + i][kk];
#pragma unroll
            for (int j = 0; j < 4; j++) kv[j] = *(const float4*)&KVs[tx + 16 * j][kk];
#pragma unroll
            for (int i = 0; i < 4; i++)
#pragma unroll
                for (int j = 0; j < 4; j++) {
                    accs[i][j] += qv[i].x * kv[j].x + qv[i].y * kv[j].y +
                                  qv[i].z * kv[j].z + qv[i].w * kv[j].w;
                }
        }

        // causal mask + online softmax
#pragma unroll
        for (int i = 0; i < 4; i++) {
            int grow = m0 + r0 + i;
#pragma unroll
            for (int j = 0; j < 4; j++) {
                int gcol = n0 + tx + 16 * j;
                if (gcol > grow) accs[i][j] = -1e30f;
            }
            float mx = fmaxf(fmaxf(accs[i][0], accs[i][1]), fmaxf(accs[i][2], accs[i][3]));
#pragma unroll
            for (int off = 8; off; off >>= 1)
                mx = fmaxf(mx, __shfl_xor_sync(0xffffffffu, mx, off));
            float mnew = fmaxf(mrow[i], mx);
            float corr = __expf(mrow[i] - mnew);
            mrow[i] = mnew;
            float rs = 0.0f;
#pragma unroll
            for (int j = 0; j < 4; j++) {
                accs[i][j] = __expf(accs[i][j] - mnew);
                rs += accs[i][j];
            }
#pragma unroll
            for (int off = 8; off; off >>= 1) rs += __shfl_xor_sync(0xffffffffu, rs, off);
            lrow[i] = lrow[i] * corr + rs;
#pragma unroll
            for (int j = 0; j < 8; j++) acc_o[i][j] *= corr;
        }
        __syncthreads();   // everyone done reading K tile

        // write P, load V tile into same buffer
#pragma unroll
        for (int i = 0; i < 4; i++)
#pragma unroll
            for (int j = 0; j < 4; j++) Ps[r0 + i][tx + 16 * j] = accs[i][j];
        for (int idx = tid; idx < 64 * 32; idx += 256) {
            int r = idx >> 5, c4 = (idx & 31) * 4;
            *(float4*)&KVs[r][c4] = *(const float4*)&vb[(size_t)(n0 + r) * (KKVH * KHD) + c4];
        }
        __syncthreads();

        // O += P @ V
        for (int kk = 0; kk < 64; kk++) {
            float4 v0 = *(const float4*)&KVs[kk][d0];
            float4 v1 = *(const float4*)&KVs[kk][d0 + 4];
#pragma unroll
            for (int i = 0; i < 4; i++) {
                float p = Ps[r0 + i][kk];
                acc_o[i][0] += p * v0.x;
                acc_o[i][1] += p * v0.y;
                acc_o[i][2] += p * v0.z;
                acc_o[i][3] += p * v0.w;
                acc_o[i][4] += p * v1.x;
                acc_o[i][5] += p * v1.y;
                acc_o[i][6] += p * v1.z;
                acc_o[i][7] += p * v1.w;
            }
        }
    }

#pragma unroll
    for (int i = 0; i < 4; i++) {
        float inv = 1.0f / lrow[i];
        size_t off = (size_t)(b * KSEQ + m0 + r0 + i) * (KNH * KHD) + head * KHD + d0;
        *(float4*)&ctx[off] = make_float4(acc_o[i][0] * inv, acc_o[i][1] * inv,
                                          acc_o[i][2] * inv, acc_o[i][3] * inv);
        *(float4*)&ctx[off + 4] = make_float4(acc_o[i][4] * inv, acc_o[i][5] * inv,
                                              acc_o[i][6] * inv, acc_o[i][7] * inv);
    }
}

// ---------------- launch ----------------
static float* sym_addr(const void* sym) {
    void* p = nullptr;
    cudaGetSymbolAddress(&p, sym);
    return (float*)p;
}

extern "C" void kernel_launch(void* const* d_in, const int* in_sizes, int n_in,
                              void* d_out, int out_size) {
    const float* hidden = (const float*)d_in[0];
    const float* sin_t  = (const float*)d_in[1];
    const float* cos_t  = (const float*)d_in[2];
    const float* w_ln1  = (const float*)d_in[3];
    const float* w_q    = (const float*)d_in[4];
    const float* w_k    = (const float*)d_in[5];
    const float* w_v    = (const float*)d_in[6];
    const float* w_o    = (const float*)d_in[7];
    const float* w_ln2  = (const float*)d_in[8];
    const float* w_gu   = (const float*)d_in[9];
    const float* w_down = (const float*)d_in[10];
    float* out = (float*)d_out;

    float* attn_in = sym_addr(g_attn_in);
    float* qbuf = sym_addr(g_q);
    float* kbuf = sym_addr(g_k);
    float* vbuf = sym_addr(g_v);
    float* ctx = sym_addr(g_ctx);
    float* mlp_in = sym_addr(g_mlp_in);
    float* gu = sym_addr(g_gu);

    // 1. attn_in = rmsnorm(hidden, w_ln1)
    rmsnorm_kernel<<<KM, 256>>>(hidden, w_ln1, attn_in);

    // 2-4. q/k/v projections
    gemm_nt<0><<<dim3(KM / BM, (KNH * KHD) / BN), 256>>>(attn_in, KHID, w_q, KHID, nullptr,
                                                         qbuf, KNH * KHD, KHID);
    gemm_nt<0><<<dim3(KM / BM, (KKVH * KHD) / BN), 256>>>(attn_in, KHID, w_k, KHID, nullptr,
                                                          kbuf, KKVH * KHD, KHID);
    gemm_nt<0><<<dim3(KM / BM, (KKVH * KHD) / BN), 256>>>(attn_in, KHID, w_v, KHID, nullptr,
                                                          vbuf, KKVH * KHD, KHID);

    // 5-6. RoPE on q and k
    {
        int tq = KM * KNH * 64;
        rope_kernel<<<(tq + 255) / 256, 256>>>(qbuf, sin_t, cos_t, KNH, tq);
        int tk = KM * KKVH * 64;
        rope_kernel<<<(tk + 255) / 256, 256>>>(kbuf, sin_t, cos_t, KKVH, tk);
    }

    // 7. attention
    {
        int smem = ATTN_SMEM_FLOATS * (int)sizeof(float);
        cudaFuncSetAttribute(attn_kernel, cudaFuncAttributeMaxDynamicSharedMemorySize, smem);
        attn_kernel<<<dim3(KSEQ / 64, KNH, KBATCH), 256, smem>>>(qbuf, kbuf, vbuf, ctx);
    }

    // 8. out = hidden + ctx @ w_o^T
    gemm_nt<0><<<dim3(KM / BM, KHID / BN), 256>>>(ctx, KNH * KHD, w_o, KNH * KHD, hidden,
                                                  out, KHID, KNH * KHD);

    // 9. mlp_in = rmsnorm(out, w_ln2)
    rmsnorm_kernel<<<KM, 256>>>(out, w_ln2, mlp_in);

    // 10. gu = mlp_in @ w_gu^T
    gemm_nt<0><<<dim3(KM / BM, (2 * KINT) / BN), 256>>>(mlp_in, KHID, w_gu, KHID, nullptr,
                                                        gu, 2 * KINT, KHID);

    // 11. out += silu(gate)*up @ w_down^T
    gemm_nt<1><<<dim3(KM / BM, KHID / BN), 256>>>(gu, 2 * KINT, w_down, KINT, out,
                                                  out, KHID, KINT);
}

// round 4
// speedup vs baseline: 2.9138x; 2.9138x over previous
#include <cuda_runtime.h>
#include <cuda_bf16.h>
#include <cstdint>
#include <math.h>

// ---------------- problem constants ----------------
#define KSEQ 1024
#define KBATCH 4
#define KHID 2048
#define KNH 16
#define KKVH 4
#define KHD 128
#define KINT 8192
#define KM (KBATCH*KSEQ)   // 4096 rows

// ---------------- scratch (device globals; no cudaMalloc allowed) ----------
__device__ __align__(256) float g_q[(size_t)KM * KNH * KHD];
__device__ __align__(256) float g_k[(size_t)KM * KKVH * KHD];
__device__ __align__(256) float g_v[(size_t)KM * KKVH * KHD];
__device__ __align__(256) float g_gu[(size_t)KM * 2 * KINT];

__device__ __align__(256) __nv_bfloat16 g_attn_h[(size_t)KM * KHID];
__device__ __align__(256) __nv_bfloat16 g_attn_l[(size_t)KM * KHID];
__device__ __align__(256) __nv_bfloat16 g_mlp_h[(size_t)KM * KHID];
__device__ __align__(256) __nv_bfloat16 g_mlp_l[(size_t)KM * KHID];
__device__ __align__(256) __nv_bfloat16 g_ctx_h[(size_t)KM * KHID];
__device__ __align__(256) __nv_bfloat16 g_ctx_l[(size_t)KM * KHID];
__device__ __align__(256) __nv_bfloat16 g_hu_h[(size_t)KM * KINT];
__device__ __align__(256) __nv_bfloat16 g_hu_l[(size_t)KM * KINT];

__device__ __align__(256) __nv_bfloat16 g_wq_h[2048 * 2048], g_wq_l[2048 * 2048];
__device__ __align__(256) __nv_bfloat16 g_wk_h[512 * 2048],  g_wk_l[512 * 2048];
__device__ __align__(256) __nv_bfloat16 g_wv_h[512 * 2048],  g_wv_l[512 * 2048];
__device__ __align__(256) __nv_bfloat16 g_wo_h[2048 * 2048], g_wo_l[2048 * 2048];
__device__ __align__(256) __nv_bfloat16 g_wgu_h[(size_t)16384 * 2048], g_wgu_l[(size_t)16384 * 2048];
__device__ __align__(256) __nv_bfloat16 g_wd_h[(size_t)2048 * 8192],  g_wd_l[(size_t)2048 * 8192];

// ---------------- PTX helpers (portable sm_80+ subset only) ----------------
__device__ __forceinline__ uint32_t smem_u32(const void* p) {
    uint32_t a;
    asm("{ .reg .u64 t; cvta.to.shared.u64 t, %1; cvt.u32.u64 %0, t; }" : "=r"(a) : "l"(p));
    return a;
}

#define CP_ASYNC16(dst, src) \
    asm volatile("cp.async.cg.shared.global [%0], [%1], 16;" :: "r"(dst), "l"(src))
#define CP_COMMIT() asm volatile("cp.async.commit_group;" ::: "memory")

#define LDMX4(r, addr) \
    asm volatile("ldmatrix.sync.aligned.m8n8.x4.shared.b16 {%0,%1,%2,%3}, [%4];" \
        : "=r"((r)[0]), "=r"((r)[1]), "=r"((r)[2]), "=r"((r)[3]) : "r"(addr))

#define MMA16816(d, a, b0, b1) \
    asm volatile("mma.sync.aligned.m16n8k16.row.col.f32.bf16.bf16.f32 " \
        "{%0,%1,%2,%3}, {%4,%5,%6,%7}, {%8,%9}, {%0,%1,%2,%3};" \
        : "+f"((d)[0]), "+f"((d)[1]), "+f"((d)[2]), "+f"((d)[3]) \
        : "r"((a)[0]), "r"((a)[1]), "r"((a)[2]), "r"((a)[3]), "r"(b0), "r"(b1))

__device__ __forceinline__ unsigned int b2u(__nv_bfloat162 v) {
    return *reinterpret_cast<unsigned int*>(&v);
}

// ---------------- fp32 -> bf16 hi/lo split ----------------
__global__ __launch_bounds__(256) void split_kernel(const float* __restrict__ x,
                                                    __nv_bfloat16* __restrict__ h,
                                                    __nv_bfloat16* __restrict__ l, int n4) {
    int i = blockIdx.x * 256 + threadIdx.x;
    if (i >= n4) return;
    float4 v = ((const float4*)x)[i];
    __nv_bfloat162 h0 = __floats2bfloat162_rn(v.x, v.y);
    __nv_bfloat162 h1 = __floats2bfloat162_rn(v.z, v.w);
    float2 f0 = __bfloat1622float2(h0), f1 = __bfloat1622float2(h1);
    __nv_bfloat162 l0 = __floats2bfloat162_rn(v.x - f0.x, v.y - f0.y);
    __nv_bfloat162 l1 = __floats2bfloat162_rn(v.z - f1.x, v.w - f1.y);
    ((uint2*)h)[i] = make_uint2(b2u(h0), b2u(h1));
    ((uint2*)l)[i] = make_uint2(b2u(l0), b2u(l1));
}

// ---------------- RMSNorm -> bf16 hi/lo ----------------
__global__ __launch_bounds__(256) void rmsnorm_split_kernel(const float* __restrict__ x,
                                                            const float* __restrict__ w,
                                                            __nv_bfloat16* __restrict__ yh,
                                                            __nv_bfloat16* __restrict__ yl) {
    int row = blockIdx.x;
    const float4* xr = (const float4*)(x + (size_t)row * KHID);
    const float4* w4 = (const float4*)w;
    int t = threadIdx.x;

    float4 a = xr[t];
    float4 b = xr[t + 256];
    float ss = a.x*a.x + a.y*a.y + a.z*a.z + a.w*a.w +
               b.x*b.x + b.y*b.y + b.z*b.z + b.w*b.w;
#pragma unroll
    for (int off = 16; off; off >>= 1) ss += __shfl_xor_sync(0xffffffffu, ss, off);
    __shared__ float wsum[8];
    if ((t & 31) == 0) wsum[t >> 5] = ss;
    __syncthreads();
    float tot = wsum[0]+wsum[1]+wsum[2]+wsum[3]+wsum[4]+wsum[5]+wsum[6]+wsum[7];
    float inv = rsqrtf(tot * (1.0f / KHID) + 1e-6f);

    float4 wa = w4[t], wb = w4[t + 256];
    float4 y0 = make_float4(a.x*inv*wa.x, a.y*inv*wa.y, a.z*inv*wa.z, a.w*inv*wa.w);
    float4 y1 = make_float4(b.x*inv*wb.x, b.y*inv*wb.y, b.z*inv*wb.z, b.w*inv*wb.w);

    size_t u0 = (size_t)row * 512 + t;
    {
        __nv_bfloat162 h0 = __floats2bfloat162_rn(y0.x, y0.y);
        __nv_bfloat162 h1 = __floats2bfloat162_rn(y0.z, y0.w);
        float2 f0 = __bfloat1622float2(h0), f1 = __bfloat1622float2(h1);
        __nv_bfloat162 l0 = __floats2bfloat162_rn(y0.x - f0.x, y0.y - f0.y);
        __nv_bfloat162 l1 = __floats2bfloat162_rn(y0.z - f1.x, y0.w - f1.y);
        ((uint2*)yh)[u0] = make_uint2(b2u(h0), b2u(h1));
        ((uint2*)yl)[u0] = make_uint2(b2u(l0), b2u(l1));
    }
    {
        __nv_bfloat162 h0 = __floats2bfloat162_rn(y1.x, y1.y);
        __nv_bfloat162 h1 = __floats2bfloat162_rn(y1.z, y1.w);
        float2 f0 = __bfloat1622float2(h0), f1 = __bfloat1622float2(h1);
        __nv_bfloat162 l0 = __floats2bfloat162_rn(y1.x - f0.x, y1.y - f0.y);
        __nv_bfloat162 l1 = __floats2bfloat162_rn(y1.z - f1.x, y1.w - f1.y);
        ((uint2*)yh)[u0 + 256] = make_uint2(b2u(h0), b2u(h1));
        ((uint2*)yl)[u0 + 256] = make_uint2(b2u(l0), b2u(l1));
    }
}

// ---------------- silu(gate)*up -> bf16 hi/lo ----------------
__global__ __launch_bounds__(256) void silu_split_kernel(const float* __restrict__ gu,
                                                         __nv_bfloat16* __restrict__ oh,
                                                         __nv_bfloat16* __restrict__ ol) {
    int i = blockIdx.x * 256 + threadIdx.x;      // over KM*KINT/4
    int row = i >> 11;                            // KINT/4 = 2048
    int c4 = (i & 2047) * 4;
    const float* base = gu + (size_t)row * (2 * KINT);
    float4 g = *(const float4*)&base[c4];
    float4 u = *(const float4*)&base[c4 + KINT];
    float p0 = (g.x / (1.0f + __expf(-g.x))) * u.x;
    float p1 = (g.y / (1.0f + __expf(-g.y))) * u.y;
    float p2 = (g.z / (1.0f + __expf(-g.z))) * u.z;
    float p3 = (g.w / (1.0f + __expf(-g.w))) * u.w;
    __nv_bfloat162 h0 = __floats2bfloat162_rn(p0, p1);
    __nv_bfloat162 h1 = __floats2bfloat162_rn(p2, p3);
    float2 f0 = __bfloat1622float2(h0), f1 = __bfloat1622float2(h1);
    __nv_bfloat162 l0 = __floats2bfloat162_rn(p0 - f0.x, p1 - f0.y);
    __nv_bfloat162 l1 = __floats2bfloat162_rn(p2 - f1.x, p3 - f1.y);
    size_t o = (size_t)row * 2048 + (c4 >> 2);
    ((uint2*)oh)[o] = make_uint2(b2u(h0), b2u(h1));
    ((uint2*)ol)[o] = make_uint2(b2u(l0), b2u(l1));
}

// ---------------- RoPE (in place) ----------------
__global__ void rope_kernel(float* __restrict__ x, const float* __restrict__ sin_t,
                            const float* __restrict__ cos_t, int nheads, int total) {
    int idx = blockIdx.x * blockDim.x + threadIdx.x;
    if (idx >= total) return;
    int half = idx & 63;
    int t2 = idx >> 6;
    int hh = t2 % nheads;
    int row = t2 / nheads;
    int s = row & (KSEQ - 1);
    float* p = x + (size_t)row * nheads * KHD + hh * KHD;
    float c = cos_t[s * 64 + half];
    float si = sin_t[s * 64 + half];
    float x1 = p[half], x2 = p[half + 64];
    p[half] = x1 * c - x2 * si;
    p[half + 64] = x2 * c + x1 * si;
}

// ---------------- mma.sync split-bf16 GEMM ----------------
// C[M,N] = (Ah+Al)[M,K] @ (Bh+Bl)[N,K]^T (+R), fp32 out.
// 128x128 block, BK=32, 8 warps (2x4), warp tile 64x32, 3-term accumulate.
#define NSTAGE 3
#define STAGE_BYTES 32768            // Ah|Al|Bh|Bl, each 128x32x2B = 8KB
#define GEMM_SMEM (NSTAGE * STAGE_BYTES)

__device__ __forceinline__ uint32_t sw_off(int row, int ch) {
    return (uint32_t)(row * 64 + ((ch ^ ((row >> 1) & 3)) << 4));
}

__global__ __launch_bounds__(256, 2) void gemm_mma(
    const __nv_bfloat16* __restrict__ Ah, const __nv_bfloat16* __restrict__ Al, int K,
    const __nv_bfloat16* __restrict__ Bh, const __nv_bfloat16* __restrict__ Bl,
    const float* __restrict__ R, float* __restrict__ C, int ldc) {
    extern __shared__ char smem[];
    uint32_t sb = smem_u32(smem);
    int tid = threadIdx.x, lane = tid & 31, wid = tid >> 5;
    int bm = blockIdx.x * 128, bn = blockIdx.y * 128;
    int wm = (wid & 1) * 64, wn = (wid >> 1) * 32;

    const __nv_bfloat16* gA_h = Ah + (size_t)bm * K;
    const __nv_bfloat16* gA_l = Al + (size_t)bm * K;
    const __nv_bfloat16* gB_h = Bh + (size_t)bn * K;
    const __nv_bfloat16* gB_l = Bl + (size_t)bn * K;

    float acc[4][4][4];
#pragma unroll
    for (int i = 0; i < 4; i++)
#pragma unroll
        for (int j = 0; j < 4; j++)
#pragma unroll
            for (int q = 0; q < 4; q++) acc[i][j][q] = 0.0f;

    int S = K >> 5;

    auto load_stage = [&](int s, int buf) {
        int k0 = s << 5;
        uint32_t st = sb + buf * STAGE_BYTES;
        const __nv_bfloat16* gps[4] = {gA_h, gA_l, gB_h, gB_l};
#pragma unroll
        for (int t = 0; t < 4; t++) {
#pragma unroll
            for (int u = 0; u < 2; u++) {
                int idx = tid + u * 256;           // 0..511
                int row = idx >> 2, ch = idx & 3;
                uint32_t dst = st + t * 8192 + sw_off(row, ch);
                CP_ASYNC16(dst, gps[t] + (size_t)row * K + k0 + ch * 8);
            }
        }
        CP_COMMIT();
    };

#pragma unroll
    for (int s = 0; s < NSTAGE - 1; s++) load_stage(s, s);

    for (int kt = 0; kt < S; kt++) {
        asm volatile("cp.async.wait_group %0;" :: "n"(NSTAGE - 2));
        __syncthreads();
        int nb = kt + NSTAGE - 1;
        if (nb < S) load_stage(nb, nb % NSTAGE);
        uint32_t st = sb + (kt % NSTAGE) * STAGE_BYTES;

#pragma unroll
        for (int kk = 0; kk < 2; kk++) {
            uint32_t bh[2][4], bl[2][4];
#pragma unroll
            for (int p = 0; p < 2; p++) {
                int row = wn + p * 16 + (lane & 7) + ((lane >> 4) << 3);
                int ch = kk * 2 + ((lane >> 3) & 1);
                uint32_t a = st + 16384 + sw_off(row, ch);
                LDMX4(bh[p], a);
                LDMX4(bl[p], a + 8192);
            }
#pragma unroll
            for (int i = 0; i < 4; i++) {
                int row = wm + i * 16 + (lane & 15);
                int ch = kk * 2 + (lane >> 4);
                uint32_t a = st + sw_off(row, ch);
                uint32_t ah[4], al[4];
                LDMX4(ah, a);
                LDMX4(al, a + 8192);
#pragma unroll
                for (int j = 0; j < 4; j++) {
                    uint32_t b0h = bh[j >> 1][(j & 1) * 2], b1h = bh[j >> 1][(j & 1) * 2 + 1];
                    uint32_t b0l = bl[j >> 1][(j & 1) * 2], b1l = bl[j >> 1][(j & 1) * 2 + 1];
                    MMA16816(acc[i][j], ah, b0h, b1h);
                    MMA16816(acc[i][j], ah, b0l, b1l);
                    MMA16816(acc[i][j], al, b0h, b1h);
                }
            }
        }
    }

    asm volatile("cp.async.wait_group 0;" ::: "memory");
    __syncthreads();

    // epilogue
#pragma unroll
    for (int i = 0; i < 4; i++) {
        int r0 = bm + wm + i * 16 + (lane >> 2);
#pragma unroll
        for (int j = 0; j < 4; j++) {
            int c0 = bn + wn + j * 8 + (lane & 3) * 2;
            float2 v0 = make_float2(acc[i][j][0], acc[i][j][1]);
            float2 v1 = make_float2(acc[i][j][2], acc[i][j][3]);
            size_t o0 = (size_t)r0 * ldc + c0;
            size_t o1 = (size_t)(r0 + 8) * ldc + c0;
            if (R != nullptr) {
                float2 q0 = *(const float2*)&R[o0];
                float2 q1 = *(const float2*)&R[o1];
                v0.x += q0.x; v0.y += q0.y;
                v1.x += q1.x; v1.y += q1.y;
            }
            *(float2*)&C[o0] = v0;
            *(float2*)&C[o1] = v1;
        }
    }
}

// ---------------- causal GQA flash attention, fp32, bf16 hi/lo output ------
#define ATTN_SMEM_FLOATS (2 * 64 * 132 + 64 * 68)

__global__ __launch_bounds__(256) void attn_kernel(const float* __restrict__ q,
                                                   const float* __restrict__ kmat,
                                                   const float* __restrict__ vmat,
                                                   __nv_bfloat16* __restrict__ ch,
                                                   __nv_bfloat16* __restrict__ cl) {
    extern __shared__ float sm[];
    float(*Qs)[132] = (float(*)[132])sm;
    float(*KVs)[132] = (float(*)[132])(sm + 64 * 132);
    float(*Ps)[68] = (float(*)[68])(sm + 2 * 64 * 132);

    int m0 = blockIdx.x * 64;
    int head = blockIdx.y;
    int b = blockIdx.z;
    int kvh = head >> 2;
    const float* qb = q + (size_t)(b * KSEQ + m0) * (KNH * KHD) + head * KHD;
    const float* kb = kmat + (size_t)(b * KSEQ) * (KKVH * KHD) + kvh * KHD;
    const float* vb = vmat + (size_t)(b * KSEQ) * (KKVH * KHD) + kvh * KHD;

    int tid = threadIdx.x;
    int ty = tid >> 4, tx = tid & 15;
    int r0 = ty * 4;
    int d0 = tx * 8;
    const float scale = 0.08838834764831845f;

    for (int idx = tid; idx < 64 * 32; idx += 256) {
        int r = idx >> 5, c4 = (idx & 31) * 4;
        float4 v = *(const float4*)&qb[(size_t)r * (KNH * KHD) + c4];
        v.x *= scale; v.y *= scale; v.z *= scale; v.w *= scale;
        *(float4*)&Qs[r][c4] = v;
    }

    float acc_o[4][8];
#pragma unroll
    for (int i = 0; i < 4; i++)
#pragma unroll
        for (int j = 0; j < 8; j++) acc_o[i][j] = 0.0f;
    float mrow[4], lrow[4];
#pragma unroll
    for (int i = 0; i < 4; i++) { mrow[i] = -1e30f; lrow[i] = 0.0f; }

    int ntiles = blockIdx.x + 1;
    for (int nt = 0; nt < ntiles; nt++) {
        int n0 = nt * 64;
        __syncthreads();
        for (int idx = tid; idx < 64 * 32; idx += 256) {
            int r = idx >> 5, c4 = (idx & 31) * 4;
            *(float4*)&KVs[r][c4] = *(const float4*)&kb[(size_t)(n0 + r) * (KKVH * KHD) + c4];
        }
        __syncthreads();

        float accs[4][4];
#pragma unroll
        for (int i = 0; i < 4; i++)
#pragma unroll
            for (int j = 0; j < 4; j++) accs[i][j] = 0.0f;

        for (int kk = 0; kk < 128; kk += 4) {
            float4 qv[4], kv[4];
#pragma unroll
            for (int i = 0; i < 4; i++) qv[i] = *(const float4*)&Qs[r0 + i][kk];
#pragma unroll
            for (int j = 0; j < 4; j++) kv[j] = *(const float4*)&KVs[tx + 16 * j][kk];
#pragma unroll
            for (int i = 0; i < 4; i++)
#pragma unroll
                for (int j = 0; j < 4; j++) {
                    accs[i][j] += qv[i].x * kv[j].x + qv[i].y * kv[j].y +
                                  qv[i].z * kv[j].z + qv[i].w * kv[j].w;
                }
        }

#pragma unroll
        for (int i = 0; i < 4; i++) {
            int grow = m0 + r0 + i;
#pragma unroll
            for (int j = 0; j < 4; j++) {
                int gcol = n0 + tx + 16 * j;
                if (gcol > grow) accs[i][j] = -1e30f;
            }
            float mx = fmaxf(fmaxf(accs[i][0], accs[i][1]), fmaxf(accs[i][2], accs[i][3]));
#pragma unroll
            for (int off = 8; off; off >>= 1)
                mx = fmaxf(mx, __shfl_xor_sync(0xffffffffu, mx, off));
            float mnew = fmaxf(mrow[i], mx);
            float corr = __expf(mrow[i] - mnew);
            mrow[i] = mnew;
            float rs = 0.0f;
#pragma unroll
            for (int j = 0; j < 4; j++) {
                accs[i][j] = __expf(accs[i][j] - mnew);
                rs += accs[i][j];
            }
#pragma unroll
            for (int off = 8; off; off >>= 1) rs += __shfl_xor_sync(0xffffffffu, rs, off);
            lrow[i] = lrow[i] * corr + rs;
#pragma unroll
            for (int j = 0; j < 8; j++) acc_o[i][j] *= corr;
        }
        __syncthreads();

#pragma unroll
        for (int i = 0; i < 4; i++)
#pragma unroll
            for (int j = 0; j < 4; j++) Ps[r0 + i][tx + 16 * j] = accs[i][j];
        for (int idx = tid; idx < 64 * 32; idx += 256) {
            int r = idx >> 5, c4 = (idx & 31) * 4;
            *(float4*)&KVs[r][c4] = *(const float4*)&vb[(size_t)(n0 + r) * (KKVH * KHD) + c4];
        }
        __syncthreads();

        for (int kk = 0; kk < 64; kk++) {
            float4 v0 = *(const float4*)&KVs[kk][d0];
            float4 v1 = *(const float4*)&KVs[kk][d0 + 4];
#pragma unroll
            for (int i = 0; i < 4; i++) {
                float p = Ps[r0 + i][kk];
                acc_o[i][0] += p * v0.x;
                acc_o[i][1] += p * v0.y;
                acc_o[i][2] += p * v0.z;
                acc_o[i][3] += p * v0.w;
                acc_o[i][4] += p * v1.x;
                acc_o[i][5] += p * v1.y;
                acc_o[i][6] += p * v1.z;
                acc_o[i][7] += p * v1.w;
            }
        }
    }

#pragma unroll
    for (int i = 0; i < 4; i++) {
        float inv = 1.0f / lrow[i];
        size_t off = (size_t)(b * KSEQ + m0 + r0 + i) * (KNH * KHD) + head * KHD + d0;
        unsigned hs[4], ls[4];
#pragma unroll
        for (int j = 0; j < 4; j++) {
            float x0 = acc_o[i][2 * j] * inv;
            float x1 = acc_o[i][2 * j + 1] * inv;
            __nv_bfloat162 h2 = __floats2bfloat162_rn(x0, x1);
            float2 hf = __bfloat1622float2(h2);
            __nv_bfloat162 l2 = __floats2bfloat162_rn(x0 - hf.x, x1 - hf.y);
            hs[j] = b2u(h2);
            ls[j] = b2u(l2);
        }
        *(uint4*)&ch[off] = make_uint4(hs[0], hs[1], hs[2], hs[3]);
        *(uint4*)&cl[off] = make_uint4(ls[0], ls[1], ls[2], ls[3]);
    }
}

// ---------------- launch ----------------
template <typename T>
static T* sym_addr(const void* sym) {
    void* p = nullptr;
    cudaGetSymbolAddress(&p, sym);
    return (T*)p;
}

extern "C" void kernel_launch(void* const* d_in, const int* in_sizes, int n_in,
                              void* d_out, int out_size) {
    const float* hidden = (const float*)d_in[0];
    const float* sin_t  = (const float*)d_in[1];
    const float* cos_t  = (const float*)d_in[2];
    const float* w_ln1  = (const float*)d_in[3];
    const float* w_q    = (const float*)d_in[4];
    const float* w_k    = (const float*)d_in[5];
    const float* w_v    = (const float*)d_in[6];
    const float* w_o    = (const float*)d_in[7];
    const float* w_ln2  = (const float*)d_in[8];
    const float* w_gu   = (const float*)d_in[9];
    const float* w_down = (const float*)d_in[10];
    float* out = (float*)d_out;

    float* qbuf = sym_addr<float>(g_q);
    float* kbuf = sym_addr<float>(g_k);
    float* vbuf = sym_addr<float>(g_v);
    float* gu   = sym_addr<float>(g_gu);
    __nv_bfloat16* attn_h = sym_addr<__nv_bfloat16>(g_attn_h);
    __nv_bfloat16* attn_l = sym_addr<__nv_bfloat16>(g_attn_l);
    __nv_bfloat16* mlp_h = sym_addr<__nv_bfloat16>(g_mlp_h);
    __nv_bfloat16* mlp_l = sym_addr<__nv_bfloat16>(g_mlp_l);
    __nv_bfloat16* ctx_h = sym_addr<__nv_bfloat16>(g_ctx_h);
    __nv_bfloat16* ctx_l = sym_addr<__nv_bfloat16>(g_ctx_l);
    __nv_bfloat16* hu_h = sym_addr<__nv_bfloat16>(g_hu_h);
    __nv_bfloat16* hu_l = sym_addr<__nv_bfloat16>(g_hu_l);
    __nv_bfloat16* wq_h = sym_addr<__nv_bfloat16>(g_wq_h);
    __nv_bfloat16* wq_l = sym_addr<__nv_bfloat16>(g_wq_l);
    __nv_bfloat16* wk_h = sym_addr<__nv_bfloat16>(g_wk_h);
    __nv_bfloat16* wk_l = sym_addr<__nv_bfloat16>(g_wk_l);
    __nv_bfloat16* wv_h = sym_addr<__nv_bfloat16>(g_wv_h);
    __nv_bfloat16* wv_l = sym_addr<__nv_bfloat16>(g_wv_l);
    __nv_bfloat16* wo_h = sym_addr<__nv_bfloat16>(g_wo_h);
    __nv_bfloat16* wo_l = sym_addr<__nv_bfloat16>(g_wo_l);
    __nv_bfloat16* wgu_h = sym_addr<__nv_bfloat16>(g_wgu_h);
    __nv_bfloat16* wgu_l = sym_addr<__nv_bfloat16>(g_wgu_l);
    __nv_bfloat16* wd_h = sym_addr<__nv_bfloat16>(g_wd_h);
    __nv_bfloat16* wd_l = sym_addr<__nv_bfloat16>(g_wd_l);

    cudaFuncSetAttribute(gemm_mma, cudaFuncAttributeMaxDynamicSharedMemorySize, GEMM_SMEM);

    // weight splits
    split_kernel<<<(2048 * 2048 / 4 + 255) / 256, 256>>>(w_q, wq_h, wq_l, 2048 * 2048 / 4);
    split_kernel<<<(512 * 2048 / 4 + 255) / 256, 256>>>(w_k, wk_h, wk_l, 512 * 2048 / 4);
    split_kernel<<<(512 * 2048 / 4 + 255) / 256, 256>>>(w_v, wv_h, wv_l, 512 * 2048 / 4);
    split_kernel<<<(2048 * 2048 / 4 + 255) / 256, 256>>>(w_o, wo_h, wo_l, 2048 * 2048 / 4);
    split_kernel<<<(16384 * 2048 / 4 + 255) / 256, 256>>>(w_gu, wgu_h, wgu_l, 16384 * 2048 / 4);
    split_kernel<<<(2048 * 8192 / 4 + 255) / 256, 256>>>(w_down, wd_h, wd_l, 2048 * 8192 / 4);

    // rmsnorm 1 -> split
    rmsnorm_split_kernel<<<KM, 256>>>(hidden, w_ln1, attn_h, attn_l);

    // q/k/v projections (fp32 out)
    gemm_mma<<<dim3(32, 16), 256, GEMM_SMEM>>>(attn_h, attn_l, KHID, wq_h, wq_l,
                                               nullptr, qbuf, 2048);
    gemm_mma<<<dim3(32, 4), 256, GEMM_SMEM>>>(attn_h, attn_l, KHID, wk_h, wk_l,
                                              nullptr, kbuf, 512);
    gemm_mma<<<dim3(32, 4), 256, GEMM_SMEM>>>(attn_h, attn_l, KHID, wv_h, wv_l,
                                              nullptr, vbuf, 512);

    // RoPE
    {
        int tq = KM * KNH * 64;
        rope_kernel<<<(tq + 255) / 256, 256>>>(qbuf, sin_t, cos_t, KNH, tq);
        int tk = KM * KKVH * 64;
        rope_kernel<<<(tk + 255) / 256, 256>>>(kbuf, sin_t, cos_t, KKVH, tk);
    }

    // attention -> ctx hi/lo
    {
        int smembytes = ATTN_SMEM_FLOATS * (int)sizeof(float);
        cudaFuncSetAttribute(attn_kernel, cudaFuncAttributeMaxDynamicSharedMemorySize, smembytes);
        attn_kernel<<<dim3(KSEQ / 64, KNH, KBATCH), 256, smembytes>>>(qbuf, kbuf, vbuf,
                                                                      ctx_h, ctx_l);
    }

    // out = hidden + ctx @ w_o^T
    gemm_mma<<<dim3(32, 16), 256, GEMM_SMEM>>>(ctx_h, ctx_l, KHID, wo_h, wo_l,
                                               hidden, out, 2048);

    // rmsnorm 2 -> split
    rmsnorm_split_kernel<<<KM, 256>>>(out, w_ln2, mlp_h, mlp_l);

    // gu = mlp_in @ w_gu^T (fp32)
    gemm_mma<<<dim3(32, 128), 256, GEMM_SMEM>>>(mlp_h, mlp_l, KHID, wgu_h, wgu_l,
                                                nullptr, gu, 2 * KINT);

    // hu = silu(gate)*up -> bf16 hi/lo
    silu_split_kernel<<<KM * KINT / 4 / 256, 256>>>(gu, hu_h, hu_l);

    // out += hu @ w_down^T
    gemm_mma<<<dim3(32, 16), 256, GEMM_SMEM>>>(hu_h, hu_l, KINT, wd_h, wd_l,
                                               out, out, 2048);
}

// round 5
// speedup vs baseline: 3.3343x; 1.1443x over previous
#include <cuda_runtime.h>
#include <cuda_bf16.h>
#include <cstdint>
#include <math.h>

// ---------------- problem constants ----------------
#define KSEQ 1024
#define KBATCH 4
#define KHID 2048
#define KNH 16
#define KKVH 4
#define KHD 128
#define KINT 8192
#define KM (KBATCH*KSEQ)   // 4096 rows

// ---------------- scratch ----------------
__device__ __align__(256) float g_q[(size_t)KM * KNH * KHD];
__device__ __align__(256) float g_k[(size_t)KM * KKVH * KHD];
__device__ __align__(256) float g_v[(size_t)KM * KKVH * KHD];

__device__ __align__(256) __nv_bfloat16 g_qh[(size_t)KM * KNH * KHD], g_ql[(size_t)KM * KNH * KHD];
__device__ __align__(256) __nv_bfloat16 g_kh[(size_t)KM * KKVH * KHD], g_kl[(size_t)KM * KKVH * KHD];
__device__ __align__(256) __nv_bfloat16 g_vth[(size_t)KM * KKVH * KHD], g_vtl[(size_t)KM * KKVH * KHD];

__device__ __align__(256) __nv_bfloat16 g_attn_h[(size_t)KM * KHID];
__device__ __align__(256) __nv_bfloat16 g_attn_l[(size_t)KM * KHID];
__device__ __align__(256) __nv_bfloat16 g_mlp_h[(size_t)KM * KHID];
__device__ __align__(256) __nv_bfloat16 g_mlp_l[(size_t)KM * KHID];
__device__ __align__(256) __nv_bfloat16 g_ctx_h[(size_t)KM * KHID];
__device__ __align__(256) __nv_bfloat16 g_ctx_l[(size_t)KM * KHID];
__device__ __align__(256) __nv_bfloat16 g_hu_h[(size_t)KM * KINT];
__device__ __align__(256) __nv_bfloat16 g_hu_l[(size_t)KM * KINT];

__device__ __align__(256) __nv_bfloat16 g_wq_h[2048 * 2048], g_wq_l[2048 * 2048];
__device__ __align__(256) __nv_bfloat16 g_wk_h[512 * 2048],  g_wk_l[512 * 2048];
__device__ __align__(256) __nv_bfloat16 g_wv_h[512 * 2048],  g_wv_l[512 * 2048];
__device__ __align__(256) __nv_bfloat16 g_wo_h[2048 * 2048], g_wo_l[2048 * 2048];
__device__ __align__(256) __nv_bfloat16 g_wgu_h[(size_t)16384 * 2048], g_wgu_l[(size_t)16384 * 2048];
__device__ __align__(256) __nv_bfloat16 g_wd_h[(size_t)2048 * 8192],  g_wd_l[(size_t)2048 * 8192];

// ---------------- PTX helpers (sm_80+ portable) ----------------
__device__ __forceinline__ uint32_t smem_u32(const void* p) {
    uint32_t a;
    asm("{ .reg .u64 t; cvta.to.shared.u64 t, %1; cvt.u32.u64 %0, t; }" : "=r"(a) : "l"(p));
    return a;
}
#define CP_ASYNC16(dst, src) \
    asm volatile("cp.async.cg.shared.global [%0], [%1], 16;" :: "r"(dst), "l"(src))
#define CP_COMMIT() asm volatile("cp.async.commit_group;" ::: "memory")
#define CP_WAIT0() asm volatile("cp.async.wait_group 0;" ::: "memory")

#define LDMX4(r, addr) \
    asm volatile("ldmatrix.sync.aligned.m8n8.x4.shared.b16 {%0,%1,%2,%3}, [%4];" \
        : "=r"((r)[0]), "=r"((r)[1]), "=r"((r)[2]), "=r"((r)[3]) : "r"(addr))

#define MMA16816(d, a, b0, b1) \
    asm volatile("mma.sync.aligned.m16n8k16.row.col.f32.bf16.bf16.f32 " \
        "{%0,%1,%2,%3}, {%4,%5,%6,%7}, {%8,%9}, {%0,%1,%2,%3};" \
        : "+f"((d)[0]), "+f"((d)[1]), "+f"((d)[2]), "+f"((d)[3]) \
        : "r"((a)[0]), "r"((a)[1]), "r"((a)[2]), "r"((a)[3]), "r"(b0), "r"(b1))

__device__ __forceinline__ unsigned int b2u(__nv_bfloat162 v) {
    return *reinterpret_cast<unsigned int*>(&v);
}
__device__ __forceinline__ unsigned int pack_bf16(float a, float b) {
    return b2u(__floats2bfloat162_rn(a, b));
}

// ---------------- fp32 -> bf16 hi/lo split ----------------
__global__ __launch_bounds__(256) void split_kernel(const float* __restrict__ x,
                                                    __nv_bfloat16* __restrict__ h,
                                                    __nv_bfloat16* __restrict__ l, int n4) {
    int i = blockIdx.x * 256 + threadIdx.x;
    if (i >= n4) return;
    float4 v = ((const float4*)x)[i];
    __nv_bfloat162 h0 = __floats2bfloat162_rn(v.x, v.y);
    __nv_bfloat162 h1 = __floats2bfloat162_rn(v.z, v.w);
    float2 f0 = __bfloat1622float2(h0), f1 = __bfloat1622float2(h1);
    __nv_bfloat162 l0 = __floats2bfloat162_rn(v.x - f0.x, v.y - f0.y);
    __nv_bfloat162 l1 = __floats2bfloat162_rn(v.z - f1.x, v.w - f1.y);
    ((uint2*)h)[i] = make_uint2(b2u(h0), b2u(h1));
    ((uint2*)l)[i] = make_uint2(b2u(l0), b2u(l1));
}

// w_gu split with gate/up row interleave: 16-row groups (8 gate, 8 up)
__global__ __launch_bounds__(256) void split_wgu_kernel(const float* __restrict__ x,
                                                        __nv_bfloat16* __restrict__ h,
                                                        __nv_bfloat16* __restrict__ l, int n4) {
    int i = blockIdx.x * 256 + threadIdx.x;
    if (i >= n4) return;
    int in_row = i >> 9;            // 512 float4 per row (K=2048)
    int col4 = i & 511;
    int out_row;
    if (in_row < 8192) out_row = ((in_row >> 3) << 4) + (in_row & 7);
    else { int rr = in_row - 8192; out_row = ((rr >> 3) << 4) + 8 + (rr & 7); }
    size_t o = (size_t)out_row * 512 + col4;
    float4 v = ((const float4*)x)[i];
    __nv_bfloat162 h0 = __floats2bfloat162_rn(v.x, v.y);
    __nv_bfloat162 h1 = __floats2bfloat162_rn(v.z, v.w);
    float2 f0 = __bfloat1622float2(h0), f1 = __bfloat1622float2(h1);
    __nv_bfloat162 l0 = __floats2bfloat162_rn(v.x - f0.x, v.y - f0.y);
    __nv_bfloat162 l1 = __floats2bfloat162_rn(v.z - f1.x, v.w - f1.y);
    ((uint2*)h)[o] = make_uint2(b2u(h0), b2u(h1));
    ((uint2*)l)[o] = make_uint2(b2u(l0), b2u(l1));
}

// ---------------- RMSNorm -> bf16 hi/lo ----------------
__global__ __launch_bounds__(256) void rmsnorm_split_kernel(const float* __restrict__ x,
                                                            const float* __restrict__ w,
                                                            __nv_bfloat16* __restrict__ yh,
                                                            __nv_bfloat16* __restrict__ yl) {
    int row = blockIdx.x;
    const float4* xr = (const float4*)(x + (size_t)row * KHID);
    const float4* w4 = (const float4*)w;
    int t = threadIdx.x;

    float4 a = xr[t];
    float4 b = xr[t + 256];
    float ss = a.x*a.x + a.y*a.y + a.z*a.z + a.w*a.w +
               b.x*b.x + b.y*b.y + b.z*b.z + b.w*b.w;
#pragma unroll
    for (int off = 16; off; off >>= 1) ss += __shfl_xor_sync(0xffffffffu, ss, off);
    __shared__ float wsum[8];
    if ((t & 31) == 0) wsum[t >> 5] = ss;
    __syncthreads();
    float tot = wsum[0]+wsum[1]+wsum[2]+wsum[3]+wsum[4]+wsum[5]+wsum[6]+wsum[7];
    float inv = rsqrtf(tot * (1.0f / KHID) + 1e-6f);

    float4 wa = w4[t], wb = w4[t + 256];
    float4 y0 = make_float4(a.x*inv*wa.x, a.y*inv*wa.y, a.z*inv*wa.z, a.w*inv*wa.w);
    float4 y1 = make_float4(b.x*inv*wb.x, b.y*inv*wb.y, b.z*inv*wb.z, b.w*inv*wb.w);

    size_t u0 = (size_t)row * 512 + t;
    {
        __nv_bfloat162 h0 = __floats2bfloat162_rn(y0.x, y0.y);
        __nv_bfloat162 h1 = __floats2bfloat162_rn(y0.z, y0.w);
        float2 f0 = __bfloat1622float2(h0), f1 = __bfloat1622float2(h1);
        __nv_bfloat162 l0 = __floats2bfloat162_rn(y0.x - f0.x, y0.y - f0.y);
        __nv_bfloat162 l1 = __floats2bfloat162_rn(y0.z - f1.x, y0.w - f1.y);
        ((uint2*)yh)[u0] = make_uint2(b2u(h0), b2u(h1));
        ((uint2*)yl)[u0] = make_uint2(b2u(l0), b2u(l1));
    }
    {
        __nv_bfloat162 h0 = __floats2bfloat162_rn(y1.x, y1.y);
        __nv_bfloat162 h1 = __floats2bfloat162_rn(y1.z, y1.w);
        float2 f0 = __bfloat1622float2(h0), f1 = __bfloat1622float2(h1);
        __nv_bfloat162 l0 = __floats2bfloat162_rn(y1.x - f0.x, y1.y - f0.y);
        __nv_bfloat162 l1 = __floats2bfloat162_rn(y1.z - f1.x, y1.w - f1.y);
        ((uint2*)yh)[u0 + 256] = make_uint2(b2u(h0), b2u(h1));
        ((uint2*)yl)[u0 + 256] = make_uint2(b2u(l0), b2u(l1));
    }
}

// ---------------- RoPE + hi/lo split (scale folded for q) ----------------
__global__ void rope_split_kernel(const float* __restrict__ x,
                                  const float* __restrict__ sin_t,
                                  const float* __restrict__ cos_t,
                                  int nheads, int total, float scale,
                                  __nv_bfloat16* __restrict__ oh,
                                  __nv_bfloat16* __restrict__ ol) {
    int idx = blockIdx.x * blockDim.x + threadIdx.x;
    if (idx >= total) return;
    int half = idx & 63;
    int t2 = idx >> 6;
    int hh = t2 % nheads;
    int row = t2 / nheads;
    int s = row & (KSEQ - 1);
    const float* p = x + (size_t)row * nheads * KHD + hh * KHD;
    float c = cos_t[s * 64 + half];
    float si = sin_t[s * 64 + half];
    float x1 = p[half], x2 = p[half + 64];
    float y1 = (x1 * c - x2 * si) * scale;
    float y2 = (x2 * c + x1 * si) * scale;
    size_t o = (size_t)row * nheads * KHD + hh * KHD + half;
    __nv_bfloat16 h1 = __float2bfloat16_rn(y1);
    __nv_bfloat16 h2 = __float2bfloat16_rn(y2);
    oh[o] = h1;      ol[o] = __float2bfloat16_rn(y1 - __bfloat162float(h1));
    oh[o + 64] = h2; ol[o + 64] = __float2bfloat16_rn(y2 - __bfloat162float(h2));
}

// ---------------- V transpose + split: [b,s,kvh,d] fp32 -> [b,kvh,d,s] bf16 hi/lo ----
__global__ __launch_bounds__(256) void vtrans_split_kernel(const float* __restrict__ v,
                                                           __nv_bfloat16* __restrict__ oh,
                                                           __nv_bfloat16* __restrict__ ol) {
    __shared__ float tile[32][33];
    int s0 = blockIdx.x * 32;
    int d0 = (blockIdx.y & 3) * 32;
    int kvh = blockIdx.y >> 2;
    int b = blockIdx.z;
    int tx = threadIdx.x & 31, ty = threadIdx.x >> 5;   // 32 x 8
#pragma unroll
    for (int yy = 0; yy < 4; yy++) {
        int s = s0 + ty + yy * 8;
        tile[ty + yy * 8][tx] = v[(size_t)(b * KSEQ + s) * (KKVH * KHD) + kvh * KHD + d0 + tx];
    }
    __syncthreads();
#pragma unroll
    for (int yy = 0; yy < 4; yy++) {
        int d = d0 + ty + yy * 8;
        int s = s0 + tx;
        float val = tile[tx][ty + yy * 8];
        __nv_bfloat16 h = __float2bfloat16_rn(val);
        size_t o = ((size_t)(b * KKVH + kvh) * KHD + d) * KSEQ + s;
        oh[o] = h;
        ol[o] = __float2bfloat16_rn(val - __bfloat162float(h));
    }
}

// ---------------- mma.sync split-bf16 GEMM ----------------
// EPI=0: C fp32 (+R).  EPI=1: gate/up interleaved silu epilogue -> Oh/Ol bf16 (width 8192).
#define NSTAGE 3
#define STAGE_BYTES 32768
#define GEMM_SMEM (NSTAGE * STAGE_BYTES)

__device__ __forceinline__ uint32_t sw_off(int row, int ch) {
    return (uint32_t)(row * 64 + ((ch ^ ((row >> 1) & 3)) << 4));
}

template <int EPI>
__global__ __launch_bounds__(256, 2) void gemm_mma(
    const __nv_bfloat16* __restrict__ Ah, const __nv_bfloat16* __restrict__ Al, int K,
    const __nv_bfloat16* __restrict__ Bh, const __nv_bfloat16* __restrict__ Bl,
    const float* __restrict__ R, float* __restrict__ C, int ldc,
    __nv_bfloat16* __restrict__ Oh, __nv_bfloat16* __restrict__ Ol) {
    extern __shared__ char smem[];
    uint32_t sb = smem_u32(smem);
    int tid = threadIdx.x, lane = tid & 31, wid = tid >> 5;
    int bm = blockIdx.x * 128, bn = blockIdx.y * 128;
    int wm = (wid & 1) * 64, wn = (wid >> 1) * 32;

    const __nv_bfloat16* gA_h = Ah + (size_t)bm * K;
    const __nv_bfloat16* gA_l = Al + (size_t)bm * K;
    const __nv_bfloat16* gB_h = Bh + (size_t)bn * K;
    const __nv_bfloat16* gB_l = Bl + (size_t)bn * K;

    float acc[4][4][4];
#pragma unroll
    for (int i = 0; i < 4; i++)
#pragma unroll
        for (int j = 0; j < 4; j++)
#pragma unroll
            for (int q = 0; q < 4; q++) acc[i][j][q] = 0.0f;

    int S = K >> 5;

    auto load_stage = [&](int s, int buf) {
        int k0 = s << 5;
        uint32_t st = sb + buf * STAGE_BYTES;
        const __nv_bfloat16* gps[4] = {gA_h, gA_l, gB_h, gB_l};
#pragma unroll
        for (int t = 0; t < 4; t++) {
#pragma unroll
            for (int u = 0; u < 2; u++) {
                int idx = tid + u * 256;
                int row = idx >> 2, ch = idx & 3;
                uint32_t dst = st + t * 8192 + sw_off(row, ch);
                CP_ASYNC16(dst, gps[t] + (size_t)row * K + k0 + ch * 8);
            }
        }
        CP_COMMIT();
    };

#pragma unroll
    for (int s = 0; s < NSTAGE - 1; s++) load_stage(s, s);

    for (int kt = 0; kt < S; kt++) {
        asm volatile("cp.async.wait_group %0;" :: "n"(NSTAGE - 2));
        __syncthreads();
        int nb = kt + NSTAGE - 1;
        if (nb < S) load_stage(nb, nb % NSTAGE);
        uint32_t st = sb + (kt % NSTAGE) * STAGE_BYTES;

#pragma unroll
        for (int kk = 0; kk < 2; kk++) {
            uint32_t bh[2][4], bl[2][4];
#pragma unroll
            for (int p = 0; p < 2; p++) {
                int row = wn + p * 16 + (lane & 7) + ((lane >> 4) << 3);
                int ch = kk * 2 + ((lane >> 3) & 1);
                uint32_t a = st + 16384 + sw_off(row, ch);
                LDMX4(bh[p], a);
                LDMX4(bl[p], a + 8192);
            }
#pragma unroll
            for (int i = 0; i < 4; i++) {
                int row = wm + i * 16 + (lane & 15);
                int ch = kk * 2 + (lane >> 4);
                uint32_t a = st + sw_off(row, ch);
                uint32_t ah[4], al[4];
                LDMX4(ah, a);
                LDMX4(al, a + 8192);
#pragma unroll
                for (int j = 0; j < 4; j++) {
                    uint32_t b0h = bh[j >> 1][(j & 1) * 2], b1h = bh[j >> 1][(j & 1) * 2 + 1];
                    uint32_t b0l = bl[j >> 1][(j & 1) * 2], b1l = bl[j >> 1][(j & 1) * 2 + 1];
                    MMA16816(acc[i][j], ah, b0h, b1h);
                    MMA16816(acc[i][j], ah, b0l, b1l);
                    MMA16816(acc[i][j], al, b0h, b1h);
                }
            }
        }
    }

    asm volatile("cp.async.wait_group 0;" ::: "memory");
    __syncthreads();

    if (EPI == 0) {
#pragma unroll
        for (int i = 0; i < 4; i++) {
            int r0 = bm + wm + i * 16 + (lane >> 2);
#pragma unroll
            for (int j = 0; j < 4; j++) {
                int c0 = bn + wn + j * 8 + (lane & 3) * 2;
                float2 v0 = make_float2(acc[i][j][0], acc[i][j][1]);
                float2 v1 = make_float2(acc[i][j][2], acc[i][j][3]);
                size_t o0 = (size_t)r0 * ldc + c0;
                size_t o1 = (size_t)(r0 + 8) * ldc + c0;
                if (R != nullptr) {
                    float2 q0 = *(const float2*)&R[o0];
                    float2 q1 = *(const float2*)&R[o1];
                    v0.x += q0.x; v0.y += q0.y;
                    v1.x += q1.x; v1.y += q1.y;
                }
                *(float2*)&C[o0] = v0;
                *(float2*)&C[o1] = v1;
            }
        }
    } else {
        // interleaved gate/up: j even = gate block, j odd = up block (same out cols)
#pragma unroll
        for (int i = 0; i < 4; i++) {
            int r0 = bm + wm + i * 16 + (lane >> 2);
#pragma unroll
            for (int P = 0; P < 2; P++) {
                int cout = (bn >> 1) + (wn >> 1) + P * 8 + (lane & 3) * 2;
#pragma unroll
                for (int h = 0; h < 2; h++) {        // row r0, r0+8
                    float gA = acc[i][2 * P][2 * h], gB = acc[i][2 * P][2 * h + 1];
                    float uA = acc[i][2 * P + 1][2 * h], uB = acc[i][2 * P + 1][2 * h + 1];
                    float p0 = (gA / (1.0f + __expf(-gA))) * uA;
                    float p1 = (gB / (1.0f + __expf(-gB))) * uB;
                    __nv_bfloat162 h2 = __floats2bfloat162_rn(p0, p1);
                    float2 hf = __bfloat1622float2(h2);
                    __nv_bfloat162 l2 = __floats2bfloat162_rn(p0 - hf.x, p1 - hf.y);
                    size_t o = (size_t)(r0 + h * 8) * 8192 + cout;
                    *(unsigned*)&Oh[o] = b2u(h2);
                    *(unsigned*)&Ol[o] = b2u(l2);
                }
            }
        }
    }
}

// ---------------- tensor-core causal GQA flash attention (split bf16) ------
// 128 threads, 4 warps; block = 64 q rows x one (b, head). Warp S-tile 16x64.
#define ATT_SMEM (96 * 1024)
__device__ __forceinline__ uint32_t sw256(int r, int c) {
    return (uint32_t)(r * 256 + ((c ^ (r & 15)) << 4));
}
__device__ __forceinline__ uint32_t sw128a(int r, int c) {
    return (uint32_t)(r * 128 + ((c ^ (r & 7)) << 4));
}

__global__ __launch_bounds__(128) void attn_mma_kernel(
    const __nv_bfloat16* __restrict__ qh, const __nv_bfloat16* __restrict__ ql,
    const __nv_bfloat16* __restrict__ kh, const __nv_bfloat16* __restrict__ kl,
    const __nv_bfloat16* __restrict__ vth, const __nv_bfloat16* __restrict__ vtl,
    __nv_bfloat16* __restrict__ ch, __nv_bfloat16* __restrict__ cl) {
    extern __shared__ char smem[];
    uint32_t sb = smem_u32(smem);
    const uint32_t sQh = sb, sQl = sb + 16384;
    const uint32_t sKh = sb + 32768, sKl = sb + 49152;
    const uint32_t sVh = sb + 65536, sVl = sb + 81920;

    int qt = gridDim.x - 1 - blockIdx.x;     // longest blocks first
    int head = blockIdx.y, b = blockIdx.z;
    int kvh = head >> 2;
    int m0 = qt * 64;
    int tid = threadIdx.x, lane = tid & 31, wid = tid >> 5;
    int wr = wid * 16;

    const __nv_bfloat16* gq_h = qh + (size_t)(b * KSEQ + m0) * 2048 + head * 128;
    const __nv_bfloat16* gq_l = ql + (size_t)(b * KSEQ + m0) * 2048 + head * 128;
    const __nv_bfloat16* gk_h = kh + (size_t)(b * KSEQ) * 512 + kvh * 128;
    const __nv_bfloat16* gk_l = kl + (size_t)(b * KSEQ) * 512 + kvh * 128;
    const __nv_bfloat16* gv_h = vth + (size_t)(b * KKVH + kvh) * 128 * 1024;
    const __nv_bfloat16* gv_l = vtl + (size_t)(b * KKVH + kvh) * 128 * 1024;

    // load Q (both) + K tile 0, one group
#pragma unroll
    for (int u = 0; u < 8; u++) {
        int idx = tid + u * 128;
        int r = idx >> 4, c = idx & 15;
        CP_ASYNC16(sQh + sw256(r, c), gq_h + (size_t)r * 2048 + c * 8);
        CP_ASYNC16(sQl + sw256(r, c), gq_l + (size_t)r * 2048 + c * 8);
        CP_ASYNC16(sKh + sw256(r, c), gk_h + (size_t)r * 512 + c * 8);
        CP_ASYNC16(sKl + sw256(r, c), gk_l + (size_t)r * 512 + c * 8);
    }
    CP_COMMIT();

    float oacc[16][4];
#pragma unroll
    for (int j = 0; j < 16; j++)
#pragma unroll
        for (int q = 0; q < 4; q++) oacc[j][q] = 0.0f;
    float mr[2] = {-1e30f, -1e30f}, lr[2] = {0.0f, 0.0f};

    int ntiles = qt + 1;
    for (int nt = 0; nt < ntiles; nt++) {
        int n0 = nt * 64;
        CP_WAIT0();
        __syncthreads();             // K(nt) ready; all warps done with V(nt-1)

        // issue V(nt)
#pragma unroll
        for (int u = 0; u < 8; u++) {
            int idx = tid + u * 128;
            int r = idx >> 3, c = idx & 7;
            CP_ASYNC16(sVh + sw128a(r, c), gv_h + (size_t)r * 1024 + n0 + c * 8);
            CP_ASYNC16(sVl + sw128a(r, c), gv_l + (size_t)r * 1024 + n0 + c * 8);
        }
        CP_COMMIT();

        // S = Q K^T  (3-term)
        float sacc[8][4];
#pragma unroll
        for (int j = 0; j < 8; j++)
#pragma unroll
            for (int q = 0; q < 4; q++) sacc[j][q] = 0.0f;

#pragma unroll
        for (int kc = 0; kc < 8; kc++) {
            uint32_t ah[4], al[4];
            {
                int row = wr + (lane & 15);
                int chn = kc * 2 + (lane >> 4);
                LDMX4(ah, sQh + sw256(row, chn));
                LDMX4(al, sQl + sw256(row, chn));
            }
#pragma unroll
            for (int g = 0; g < 4; g++) {
                uint32_t bh[4], bl[4];
                int row = g * 16 + (lane & 7) + ((lane >> 4) << 3);
                int chn = kc * 2 + ((lane >> 3) & 1);
                LDMX4(bh, sKh + sw256(row, chn));
                LDMX4(bl, sKl + sw256(row, chn));
                MMA16816(sacc[2 * g], ah, bh[0], bh[1]);
                MMA16816(sacc[2 * g], ah, bl[0], bl[1]);
                MMA16816(sacc[2 * g], al, bh[0], bh[1]);
                MMA16816(sacc[2 * g + 1], ah, bh[2], bh[3]);
                MMA16816(sacc[2 * g + 1], ah, bl[2], bl[3]);
                MMA16816(sacc[2 * g + 1], al, bh[2], bh[3]);
            }
        }

        CP_WAIT0();
        __syncthreads();             // V ready; all warps done reading K

        // prefetch K(nt+1)
        if (nt + 1 < ntiles) {
            int n1 = n0 + 64;
#pragma unroll
            for (int u = 0; u < 8; u++) {
                int idx = tid + u * 128;
                int r = idx >> 4, c = idx & 15;
                CP_ASYNC16(sKh + sw256(r, c), gk_h + (size_t)(n1 + r) * 512 + c * 8);
                CP_ASYNC16(sKl + sw256(r, c), gk_l + (size_t)(n1 + r) * 512 + c * 8);
            }
            CP_COMMIT();
        }

        // causal mask (diagonal tile only)
        if (nt == qt) {
            int row0 = m0 + wr + (lane >> 2);
#pragma unroll
            for (int j = 0; j < 8; j++) {
                int cn = n0 + j * 8 + (lane & 3) * 2;
                if (cn > row0) sacc[j][0] = -1e30f;
                if (cn + 1 > row0) sacc[j][1] = -1e30f;
                if (cn > row0 + 8) sacc[j][2] = -1e30f;
                if (cn + 1 > row0 + 8) sacc[j][3] = -1e30f;
            }
        }

        // online softmax
        float mx0 = -1e30f, mx1 = -1e30f;
#pragma unroll
        for (int j = 0; j < 8; j++) {
            mx0 = fmaxf(mx0, fmaxf(sacc[j][0], sacc[j][1]));
            mx1 = fmaxf(mx1, fmaxf(sacc[j][2], sacc[j][3]));
        }
        mx0 = fmaxf(mx0, __shfl_xor_sync(0xffffffffu, mx0, 1));
        mx0 = fmaxf(mx0, __shfl_xor_sync(0xffffffffu, mx0, 2));
        mx1 = fmaxf(mx1, __shfl_xor_sync(0xffffffffu, mx1, 1));
        mx1 = fmaxf(mx1, __shfl_xor_sync(0xffffffffu, mx1, 2));
        float mn0 = fmaxf(mr[0], mx0), mn1 = fmaxf(mr[1], mx1);
        float cr0 = __expf(mr[0] - mn0), cr1 = __expf(mr[1] - mn1);
        mr[0] = mn0; mr[1] = mn1;
        float rs0 = 0.0f, rs1 = 0.0f;
#pragma unroll
        for (int j = 0; j < 8; j++) {
            sacc[j][0] = __expf(sacc[j][0] - mn0);
            sacc[j][1] = __expf(sacc[j][1] - mn0);
            sacc[j][2] = __expf(sacc[j][2] - mn1);
            sacc[j][3] = __expf(sacc[j][3] - mn1);
            rs0 += sacc[j][0] + sacc[j][1];
            rs1 += sacc[j][2] + sacc[j][3];
        }
        rs0 += __shfl_xor_sync(0xffffffffu, rs0, 1);
        rs0 += __shfl_xor_sync(0xffffffffu, rs0, 2);
        rs1 += __shfl_xor_sync(0xffffffffu, rs1, 1);
        rs1 += __shfl_xor_sync(0xffffffffu, rs1, 2);
        lr[0] = lr[0] * cr0 + rs0;
        lr[1] = lr[1] * cr1 + rs1;
#pragma unroll
        for (int j = 0; j < 16; j++) {
            oacc[j][0] *= cr0; oacc[j][1] *= cr0;
            oacc[j][2] *= cr1; oacc[j][3] *= cr1;
        }

        // P -> A-frags (hi/lo), register-only reshuffle
        uint32_t ph[4][4], pl[4][4];
#pragma unroll
        for (int kc2 = 0; kc2 < 4; kc2++) {
#pragma unroll
            for (int half = 0; half < 2; half++) {    // n-block 2kc2 + half
                int j = 2 * kc2 + half;
                float v0 = sacc[j][0], v1 = sacc[j][1], v2 = sacc[j][2], v3 = sacc[j][3];
                unsigned h01 = pack_bf16(v0, v1);
                unsigned h23 = pack_bf16(v2, v3);
                __nv_bfloat162 hh01 = *(__nv_bfloat162*)&h01;
                __nv_bfloat162 hh23 = *(__nv_bfloat162*)&h23;
                float2 f01 = __bfloat1622float2(hh01);
                float2 f23 = __bfloat1622float2(hh23);
                ph[kc2][half * 2 + 0] = h01;           // a0/a2: row r
                ph[kc2][half * 2 + 1] = h23;           // a1/a3: row r+8
                pl[kc2][half * 2 + 0] = pack_bf16(v0 - f01.x, v1 - f01.y);
                pl[kc2][half * 2 + 1] = pack_bf16(v2 - f23.x, v3 - f23.y);
            }
        }
        // reorder: A-frag wants {a0=row r k0-7, a1=row r+8 k0-7, a2=row r k8-15, a3=row r+8 k8-15}
        // currently [0]=r blk0, [1]=r+8 blk0, [2]=r blk1, [3]=r+8 blk1 — already matches (blk = k8 chunk).

        // O += P V   (3-term)
#pragma unroll
        for (int jo = 0; jo < 8; jo++) {
#pragma unroll
            for (int kc2 = 0; kc2 < 4; kc2++) {
                uint32_t vh4[4], vl4[4];
                int row = jo * 16 + (lane & 7) + ((lane >> 4) << 3);
                int chn = kc2 * 2 + ((lane >> 3) & 1);
                LDMX4(vh4, sVh + sw128a(row, chn));
                LDMX4(vl4, sVl + sw128a(row, chn));
                uint32_t pa[4] = {ph[kc2][0], ph[kc2][1], ph[kc2][2], ph[kc2][3]};
                uint32_t pb[4] = {pl[kc2][0], pl[kc2][1], pl[kc2][2], pl[kc2][3]};
                MMA16816(oacc[2 * jo], pa, vh4[0], vh4[1]);
                MMA16816(oacc[2 * jo], pb, vh4[0], vh4[1]);
                MMA16816(oacc[2 * jo], pa, vl4[0], vl4[1]);
                MMA16816(oacc[2 * jo + 1], pa, vh4[2], vh4[3]);
                MMA16816(oacc[2 * jo + 1], pb, vh4[2], vh4[3]);
                MMA16816(oacc[2 * jo + 1], pa, vl4[2], vl4[3]);
            }
        }
    }

    // epilogue: O/l -> bf16 hi/lo ctx
    float inv0 = 1.0f / lr[0], inv1 = 1.0f / lr[1];
    size_t row0 = (size_t)(b * KSEQ + m0 + wr + (lane >> 2));
    size_t row1 = row0 + 8;
#pragma unroll
    for (int jo = 0; jo < 16; jo++) {
        int col = head * 128 + jo * 8 + (lane & 3) * 2;
        float x0 = oacc[jo][0] * inv0, x1 = oacc[jo][1] * inv0;
        float x2 = oacc[jo][2] * inv1, x3 = oacc[jo][3] * inv1;
        __nv_bfloat162 h0 = __floats2bfloat162_rn(x0, x1);
        __nv_bfloat162 h1 = __floats2bfloat162_rn(x2, x3);
        float2 f0 = __bfloat1622float2(h0), f1 = __bfloat1622float2(h1);
        *(unsigned*)&ch[row0 * 2048 + col] = b2u(h0);
        *(unsigned*)&cl[row0 * 2048 + col] = b2u(__floats2bfloat162_rn(x0 - f0.x, x1 - f0.y));
        *(unsigned*)&ch[row1 * 2048 + col] = b2u(h1);
        *(unsigned*)&cl[row1 * 2048 + col] = b2u(__floats2bfloat162_rn(x2 - f1.x, x3 - f1.y));
    }
}

// ---------------- launch ----------------
template <typename T>
static T* sym_addr(const void* sym) {
    void* p = nullptr;
    cudaGetSymbolAddress(&p, sym);
    return (T*)p;
}

extern "C" void kernel_launch(void* const* d_in, const int* in_sizes, int n_in,
                              void* d_out, int out_size) {
    const float* hidden = (const float*)d_in[0];
    const float* sin_t  = (const float*)d_in[1];
    const float* cos_t  = (const float*)d_in[2];
    const float* w_ln1  = (const float*)d_in[3];
    const float* w_q    = (const float*)d_in[4];
    const float* w_k    = (const float*)d_in[5];
    const float* w_v    = (const float*)d_in[6];
    const float* w_o    = (const float*)d_in[7];
    const float* w_ln2  = (const float*)d_in[8];
    const float* w_gu   = (const float*)d_in[9];
    const float* w_down = (const float*)d_in[10];
    float* out = (float*)d_out;

    float* qbuf = sym_addr<float>(g_q);
    float* kbuf = sym_addr<float>(g_k);
    float* vbuf = sym_addr<float>(g_v);
    __nv_bfloat16* qhb = sym_addr<__nv_bfloat16>(g_qh);
    __nv_bfloat16* qlb = sym_addr<__nv_bfloat16>(g_ql);
    __nv_bfloat16* khb = sym_addr<__nv_bfloat16>(g_kh);
    __nv_bfloat16* klb = sym_addr<__nv_bfloat16>(g_kl);
    __nv_bfloat16* vthb = sym_addr<__nv_bfloat16>(g_vth);
    __nv_bfloat16* vtlb = sym_addr<__nv_bfloat16>(g_vtl);
    __nv_bfloat16* attn_h = sym_addr<__nv_bfloat16>(g_attn_h);
    __nv_bfloat16* attn_l = sym_addr<__nv_bfloat16>(g_attn_l);
    __nv_bfloat16* mlp_h = sym_addr<__nv_bfloat16>(g_mlp_h);
    __nv_bfloat16* mlp_l = sym_addr<__nv_bfloat16>(g_mlp_l);
    __nv_bfloat16* ctx_h = sym_addr<__nv_bfloat16>(g_ctx_h);
    __nv_bfloat16* ctx_l = sym_addr<__nv_bfloat16>(g_ctx_l);
    __nv_bfloat16* hu_h = sym_addr<__nv_bfloat16>(g_hu_h);
    __nv_bfloat16* hu_l = sym_addr<__nv_bfloat16>(g_hu_l);
    __nv_bfloat16* wq_h = sym_addr<__nv_bfloat16>(g_wq_h);
    __nv_bfloat16* wq_l = sym_addr<__nv_bfloat16>(g_wq_l);
    __nv_bfloat16* wk_h = sym_addr<__nv_bfloat16>(g_wk_h);
    __nv_bfloat16* wk_l = sym_addr<__nv_bfloat16>(g_wk_l);
    __nv_bfloat16* wv_h = sym_addr<__nv_bfloat16>(g_wv_h);
    __nv_bfloat16* wv_l = sym_addr<__nv_bfloat16>(g_wv_l);
    __nv_bfloat16* wo_h = sym_addr<__nv_bfloat16>(g_wo_h);
    __nv_bfloat16* wo_l = sym_addr<__nv_bfloat16>(g_wo_l);
    __nv_bfloat16* wgu_h = sym_addr<__nv_bfloat16>(g_wgu_h);
    __nv_bfloat16* wgu_l = sym_addr<__nv_bfloat16>(g_wgu_l);
    __nv_bfloat16* wd_h = sym_addr<__nv_bfloat16>(g_wd_h);
    __nv_bfloat16* wd_l = sym_addr<__nv_bfloat16>(g_wd_l);

    cudaFuncSetAttribute(gemm_mma<0>, cudaFuncAttributeMaxDynamicSharedMemorySize, GEMM_SMEM);
    cudaFuncSetAttribute(gemm_mma<1>, cudaFuncAttributeMaxDynamicSharedMemorySize, GEMM_SMEM);
    cudaFuncSetAttribute(attn_mma_kernel, cudaFuncAttributeMaxDynamicSharedMemorySize, ATT_SMEM);

    // launches 0-3: small weight splits
    split_kernel<<<(2048 * 2048 / 4 + 255) / 256, 256>>>(w_q, wq_h, wq_l, 2048 * 2048 / 4);
    split_kernel<<<(512 * 2048 / 4 + 255) / 256, 256>>>(w_k, wk_h, wk_l, 512 * 2048 / 4);
    split_kernel<<<(512 * 2048 / 4 + 255) / 256, 256>>>(w_v, wv_h, wv_l, 512 * 2048 / 4);
    split_kernel<<<(2048 * 2048 / 4 + 255) / 256, 256>>>(w_o, wo_h, wo_l, 2048 * 2048 / 4);
    // launch 4: rmsnorm1
    rmsnorm_split_kernel<<<KM, 256>>>(hidden, w_ln1, attn_h, attn_l);
    // launch 5: Q GEMM  <- ncu -s 5 -c 1 capture target
    gemm_mma<0><<<dim3(32, 16), 256, GEMM_SMEM>>>(attn_h, attn_l, KHID, wq_h, wq_l,
                                                  nullptr, qbuf, 2048, nullptr, nullptr);
    gemm_mma<0><<<dim3(32, 4), 256, GEMM_SMEM>>>(attn_h, attn_l, KHID, wk_h, wk_l,
                                                 nullptr, kbuf, 512, nullptr, nullptr);
    gemm_mma<0><<<dim3(32, 4), 256, GEMM_SMEM>>>(attn_h, attn_l, KHID, wv_h, wv_l,
                                                 nullptr, vbuf, 512, nullptr, nullptr);

    // rope + split
    {
        const float qscale = 0.08838834764831845f;   // 1/sqrt(128)
        int tq = KM * KNH * 64;
        rope_split_kernel<<<(tq + 255) / 256, 256>>>(qbuf, sin_t, cos_t, KNH, tq, qscale,
                                                     qhb, qlb);
        int tk = KM * KKVH * 64;
        rope_split_kernel<<<(tk + 255) / 256, 256>>>(kbuf, sin_t, cos_t, KKVH, tk, 1.0f,
                                                     khb, klb);
    }
    // V transpose + split
    vtrans_split_kernel<<<dim3(KSEQ / 32, KKVH * 4, KBATCH), 256>>>(vbuf, vthb, vtlb);

    // tensor-core attention
    attn_mma_kernel<<<dim3(KSEQ / 64, KNH, KBATCH), 128, ATT_SMEM>>>(qhb, qlb, khb, klb,
                                                                     vthb, vtlb, ctx_h, ctx_l);

    // out = hidden + ctx @ w_o^T
    gemm_mma<0><<<dim3(32, 16), 256, GEMM_SMEM>>>(ctx_h, ctx_l, KHID, wo_h, wo_l,
                                                  hidden, out, 2048, nullptr, nullptr);

    // rmsnorm2
    rmsnorm_split_kernel<<<KM, 256>>>(out, w_ln2, mlp_h, mlp_l);

    // interleaved gate/up split + fused silu GEMM -> hu hi/lo
    split_wgu_kernel<<<(16384 * 2048 / 4 + 255) / 256, 256>>>(w_gu, wgu_h, wgu_l,
                                                              16384 * 2048 / 4);
    gemm_mma<1><<<dim3(32, 128), 256, GEMM_SMEM>>>(mlp_h, mlp_l, KHID, wgu_h, wgu_l,
                                                   nullptr, nullptr, 0, hu_h, hu_l);

    // down projection + residual
    split_kernel<<<(2048 * 8192 / 4 + 255) / 256, 256>>>(w_down, wd_h, wd_l, 2048 * 8192 / 4);
    gemm_mma<0><<<dim3(32, 16), 256, GEMM_SMEM>>>(hu_h, hu_l, KINT, wd_h, wd_l,
                                                  out, out, 2048, nullptr, nullptr);
}